// round 15
// baseline (speedup 1.0000x reference)
#include <cuda_runtime.h>
#include <cuda_fp16.h>
#include <math_constants.h>
#include <cstdint>

#define N_NODES 100000
#define N_EDGES 1600000
#define IN_F    128
#define OUT_F   128     // HEADS * D_K = 4 * 32
#define NB_SCAN ((N_NODES + 1023) / 1024)   // 98
#define NTILES  ((N_NODES + 127) / 128)     // 782

// ---------------- scratch (no allocations allowed) ----------------
__device__ __half g_Qh[N_NODES * OUT_F];    // Q gathered in fp16
__device__ float  g_K[N_NODES * OUT_F];     // K fp32 (read once per node)
__device__ __half g_Vh[N_NODES * OUT_F];    // V gathered in fp16
__device__ int    g_cnt[N_NODES];
__device__ int    g_off[N_NODES + 1];
__device__ int    g_cur[N_NODES];
__device__ int    g_src[N_EDGES];
__device__ unsigned long long g_part[NB_SCAN];  // lookback: (sum<<2)|state
__device__ int    g_is64;
// single-fp16 weight images, row-major [out_feature][128]
__device__ __half g_Wh[3][OUT_F * IN_F];

// ---------------- mma.sync helpers (base sm_103 legal) ----------------
__device__ __forceinline__ uint32_t smem_u32(const void* p)
{
    uint32_t a;
    asm("{ .reg .u64 t; cvta.to.shared.u64 t, %1; cvt.u32.u64 %0, t; }"
        : "=r"(a) : "l"(p));
    return a;
}
__device__ __forceinline__ void ldsm4(uint32_t& r0, uint32_t& r1, uint32_t& r2,
                                      uint32_t& r3, uint32_t addr)
{
    asm volatile("ldmatrix.sync.aligned.m8n8.x4.shared.b16 {%0,%1,%2,%3}, [%4];"
                 : "=r"(r0), "=r"(r1), "=r"(r2), "=r"(r3) : "r"(addr));
}
__device__ __forceinline__ void mma16816(float* c,
                                         uint32_t a0, uint32_t a1, uint32_t a2, uint32_t a3,
                                         uint32_t b0, uint32_t b1)
{
    asm volatile("mma.sync.aligned.m16n8k16.row.col.f32.f16.f16.f32 "
                 "{%0,%1,%2,%3}, {%4,%5,%6,%7}, {%8,%9}, {%0,%1,%2,%3};"
                 : "+f"(c[0]), "+f"(c[1]), "+f"(c[2]), "+f"(c[3])
                 : "r"(a0), "r"(a1), "r"(a2), "r"(a3), "r"(b0), "r"(b1));
}
// 256B-row swizzled chunk offset: 16 chunks of 16B, low-3 chunk bits XOR row&7
__device__ __forceinline__ uint32_t sw256(int row, int ch)
{
    return (uint32_t)(row << 8) + (uint32_t)(((ch & 8) | ((ch & 7) ^ (row & 7))) << 4);
}

// zero counters + lookback states + detect edge dtype (thread 0)
__global__ void k_zero(const void* __restrict__ ei)
{
    int i = blockIdx.x * blockDim.x + threadIdx.x;
    if (i < N_NODES) g_cnt[i] = 0;
    if (i < NB_SCAN) g_part[i] = 0ull;
    if (i == 0) {
        const long long* p = (const long long*)ei;
        bool ok = true;
        #pragma unroll
        for (int k = 0; k < 8; k++) {
            long long v = p[k];
            if (v < 0 || v >= N_NODES) ok = false;
        }
        g_is64 = ok ? 1 : 0;
    }
}

// ---------------- fp16 weight pre-conversion ----------------
__global__ void k_wconv(const float* __restrict__ Wq,
                        const float* __restrict__ Wk,
                        const float* __restrict__ Wv)
{
    int mat = blockIdx.x;
    const float* W = (mat == 0) ? Wq : (mat == 1) ? Wk : Wv;
    int row = threadIdx.x;            // output-feature 0..127
    #pragma unroll 4
    for (int c8 = 0; c8 < 16; c8++) {
        union { __half b[8]; uint4 v; } H;
        #pragma unroll
        for (int j = 0; j < 8; j++)
            H.b[j] = __float2half_rn(W[row * IN_F + c8 * 8 + j]);
        *(uint4*)&g_Wh[mat][row * IN_F + c8 * 8] = H.v;
    }
}

// ---------------- HMMA QKV GEMM ----------------
// grid (NTILES), 256 threads (8 warps, 32x64 warp tiles).
// A = x split into fp16 hi+lo (once per tile, full K in smem, 64KB);
// B = W single fp16 (32KB, reloaded per mat).
// Q,K: 2-term (Ahi+Alo)@B.  V: hi-only (fp16-stored anyway).
__global__ __launch_bounds__(256, 2) void qkv_hmma(const float* __restrict__ xp)
{
    extern __shared__ __align__(1024) unsigned char dsm[];
    const uint32_t sbase = smem_u32(dsm);
    const uint32_t Ah = sbase, Al = sbase + 32768, Bs = sbase + 65536;

    const int tile = blockIdx.x;
    const int tid = threadIdx.x, wid = tid >> 5, lane = tid & 31;
    const int wm = (wid & 3) * 32;        // warp M offset
    const int wn = (wid >> 2) * 64;       // warp N offset

    // ---- A: read x fp32 once, split fp16 hi/lo, store swizzled (full K) ----
    #pragma unroll
    for (int i = tid; i < 2048; i += 256) {
        int row = i >> 4, ch = i & 15;
        uint32_t dst = sw256(row, ch);
        int gr = tile * 128 + row;
        union { __half b[8]; uint4 v; } H, L;
        if (gr < N_NODES) {
            const float4 f0 = *(const float4*)&xp[(size_t)gr * IN_F + ch * 8 + 0];
            const float4 f1 = *(const float4*)&xp[(size_t)gr * IN_F + ch * 8 + 4];
            float fs[8] = {f0.x,f0.y,f0.z,f0.w,f1.x,f1.y,f1.z,f1.w};
            #pragma unroll
            for (int j = 0; j < 8; j++) {
                __half h = __float2half_rn(fs[j]);
                H.b[j] = h;
                L.b[j] = __float2half_rn(fs[j] - __half2float(h));
            }
        } else {
            H.v = make_uint4(0,0,0,0);
            L.v = make_uint4(0,0,0,0);
        }
        *(uint4*)(dsm + (Ah - sbase) + dst) = H.v;
        *(uint4*)(dsm + (Al - sbase) + dst) = L.v;
    }
    __syncthreads();

    for (int mat = 0; mat < 3; mat++) {
        const bool use_lo = (mat != 2);   // V: hi-only
        // ---- B: copy fp16 weights swizzled ----
        const __half* wsrc = g_Wh[mat];
        #pragma unroll
        for (int i = tid; i < 2048; i += 256) {
            int row = i >> 4, ch = i & 15;
            *(uint4*)(dsm + (Bs - sbase) + sw256(row, ch)) =
                *(const uint4*)&wsrc[(size_t)row * IN_F + ch * 8];
        }
        __syncthreads();

        float acc[2][8][4];
        #pragma unroll
        for (int mi = 0; mi < 2; mi++)
            #pragma unroll
            for (int nf = 0; nf < 8; nf++)
                #pragma unroll
                for (int j = 0; j < 4; j++) acc[mi][nf][j] = 0.f;

        #pragma unroll
        for (int k16 = 0; k16 < 8; k16++) {
            const int base8 = (k16 >> 2) << 3;
            const int c3 = ((k16 & 3) << 1) + (lane >> 4);
            uint32_t ah[2][4], al[2][4];
            #pragma unroll
            for (int mi = 0; mi < 2; mi++) {
                int arow = wm + mi * 16 + (lane & 15);
                uint32_t co = (uint32_t)((base8 + (c3 ^ (arow & 7))) << 4) + (uint32_t)(arow << 8);
                ldsm4(ah[mi][0], ah[mi][1], ah[mi][2], ah[mi][3], Ah + co);
                if (use_lo)
                    ldsm4(al[mi][0], al[mi][1], al[mi][2], al[mi][3], Al + co);
            }
            #pragma unroll
            for (int q = 0; q < 4; q++) {
                int brow = wn + q * 16 + (lane & 15);
                uint32_t b0, b1, b2, b3;
                ldsm4(b0, b1, b2, b3,
                      Bs + (uint32_t)(brow << 8) + (uint32_t)((base8 + (c3 ^ (brow & 7))) << 4));
                #pragma unroll
                for (int mi = 0; mi < 2; mi++) {
                    mma16816(acc[mi][q * 2 + 0], ah[mi][0], ah[mi][1], ah[mi][2], ah[mi][3], b0, b2);
                    mma16816(acc[mi][q * 2 + 1], ah[mi][0], ah[mi][1], ah[mi][2], ah[mi][3], b1, b3);
                    if (use_lo) {
                        mma16816(acc[mi][q * 2 + 0], al[mi][0], al[mi][1], al[mi][2], al[mi][3], b0, b2);
                        mma16816(acc[mi][q * 2 + 1], al[mi][0], al[mi][1], al[mi][2], al[mi][3], b1, b3);
                    }
                }
            }
        }
        __syncthreads();   // all MMAs done before B is overwritten next mat

        // ---- epilogue: c0,c1 -> (row t/4, col 2(t%4)); c2,c3 -> row+8 ----
        const int tq = lane >> 2, tr = lane & 3;
        #pragma unroll
        for (int mi = 0; mi < 2; mi++) {
            int r0 = tile * 128 + wm + mi * 16 + tq;
            #pragma unroll
            for (int nf = 0; nf < 8; nf++) {
                int col = wn + nf * 8 + tr * 2;
                if (mat == 1) {
                    if (r0 < N_NODES)
                        *(float2*)&g_K[(size_t)r0 * OUT_F + col] = make_float2(acc[mi][nf][0], acc[mi][nf][1]);
                    if (r0 + 8 < N_NODES)
                        *(float2*)&g_K[(size_t)(r0 + 8) * OUT_F + col] = make_float2(acc[mi][nf][2], acc[mi][nf][3]);
                } else {
                    __half* O = (mat == 0) ? g_Qh : g_Vh;
                    if (r0 < N_NODES)
                        *(__half2*)&O[(size_t)r0 * OUT_F + col] =
                            __floats2half2_rn(acc[mi][nf][0], acc[mi][nf][1]);
                    if (r0 + 8 < N_NODES)
                        *(__half2*)&O[(size_t)(r0 + 8) * OUT_F + col] =
                            __floats2half2_rn(acc[mi][nf][2], acc[mi][nf][3]);
                }
            }
        }
    }
}

// ---------------- CSR build -----------------
// 2 edges per thread, vectorized loads
__global__ void k_count(const void* __restrict__ ei)
{
    int e = (blockIdx.x * blockDim.x + threadIdx.x) * 2;
    if (e < N_EDGES) {
        int r0, r1;
        if (g_is64) {
            longlong2 p = *(const longlong2*)((const long long*)ei + e);
            r0 = (int)p.x; r1 = (int)p.y;
        } else {
            int2 p = *(const int2*)((const int*)ei + e);
            r0 = p.x; r1 = p.y;
        }
        if ((unsigned)r0 < N_NODES) atomicAdd(&g_cnt[r0], 1);
        if ((unsigned)r1 < N_NODES) atomicAdd(&g_cnt[r1], 1);
    }
}

// single-pass decoupled-lookback scan: writes g_off (exclusive) + g_cur + g_off[N]
__global__ __launch_bounds__(1024) void k_scanlb()
{
    __shared__ int wsum[32];
    __shared__ int s_prefix;
    const int b = blockIdx.x;
    const int i = b * 1024 + threadIdx.x;
    const int v = (i < N_NODES) ? g_cnt[i] : 0;
    const int lane = threadIdx.x & 31, w = threadIdx.x >> 5;

    int s = v;
    #pragma unroll
    for (int o = 1; o < 32; o <<= 1) {
        int t = __shfl_up_sync(0xffffffffu, s, o);
        if (lane >= o) s += t;
    }
    if (lane == 31) wsum[w] = s;
    __syncthreads();
    if (w == 0) {
        int t = wsum[lane];
        #pragma unroll
        for (int o = 1; o < 32; o <<= 1) {
            int u = __shfl_up_sync(0xffffffffu, t, o);
            if (lane >= o) t += u;
        }
        wsum[lane] = t;
    }
    __syncthreads();
    const int excl  = s - v + (w ? wsum[w - 1] : 0);
    const int total = wsum[31];

    if (threadIdx.x == 0) {
        __threadfence();
        atomicExch(&g_part[b], ((unsigned long long)(unsigned)total << 2) | 1ull);
        int pref = 0;
        for (int j = b - 1; j >= 0; ) {
            unsigned long long p;
            do { p = atomicAdd(&g_part[j], 0ull); } while ((p & 3ull) == 0ull);
            pref += (int)(p >> 2);
            if ((p & 3ull) == 2ull) break;
            j--;
        }
        __threadfence();
        atomicExch(&g_part[b], ((unsigned long long)(unsigned)(pref + total) << 2) | 2ull);
        s_prefix = pref;
    }
    __syncthreads();
    const int o = excl + s_prefix;
    if (i < N_NODES) { g_off[i] = o; g_cur[i] = o; }
    if (b == NB_SCAN - 1 && threadIdx.x == 1023) g_off[N_NODES] = s_prefix + total;
}

__global__ void k_scatter(const void* __restrict__ ei)
{
    int e = (blockIdx.x * blockDim.x + threadIdx.x) * 2;
    if (e < N_EDGES) {
        int r0, r1, c0, c1;
        if (g_is64) {
            longlong2 pr = *(const longlong2*)((const long long*)ei + e);
            longlong2 pc = *(const longlong2*)((const long long*)ei + N_EDGES + e);
            r0 = (int)pr.x; r1 = (int)pr.y; c0 = (int)pc.x; c1 = (int)pc.y;
        } else {
            int2 pr = *(const int2*)((const int*)ei + e);
            int2 pc = *(const int2*)((const int*)ei + N_EDGES + e);
            r0 = pr.x; r1 = pr.y; c0 = pc.x; c1 = pc.y;
        }
        if ((unsigned)r0 < N_NODES && (unsigned)c0 < N_NODES) {
            int p = atomicAdd(&g_cur[r0], 1);
            g_src[p] = c0;
        }
        if ((unsigned)r1 < N_NODES && (unsigned)c1 < N_NODES) {
            int p = atomicAdd(&g_cur[r1], 1);
            g_src[p] = c1;
        }
    }
}

// ---------------- per-node online-softmax aggregation -------------
// One warp per destination node; FOUR edge streams for deep MLP.
// Q fp16 (gathered), K fp32 (own node), V fp16.
__global__ __launch_bounds__(256) void k_aggregate(
    const float* __restrict__ D, float* __restrict__ out)
{
    int warp = (blockIdx.x * blockDim.x + threadIdx.x) >> 5;
    int lane = threadIdx.x & 31;
    if (warp >= N_NODES) return;
    const int r = warp;

    const int beg = g_off[r];
    const int end = g_off[r + 1];

    const float4 kv = *(const float4*)&g_K[(size_t)r * OUT_F + lane * 4];
    const float4 Dv = *(const float4*)&D[lane * 4];
    const float scale = 0.1767766952966369f;   // 1/sqrt(32)

    float  m[4], sw[4];
    float4 A[4];
    #pragma unroll
    for (int j = 0; j < 4; j++) {
        m[j] = -CUDART_INF_F; sw[j] = 0.f;
        A[j] = make_float4(0.f, 0.f, 0.f, 0.f);
    }

    int e = beg;
    for (; e + 4 <= end; e += 4) {
        int   c[4];
        uint2 uq[4], uv[4];
        #pragma unroll
        for (int j = 0; j < 4; j++) c[j] = g_src[e + j];
        #pragma unroll
        for (int j = 0; j < 4; j++) {
            uq[j] = *(const uint2*)&g_Qh[(size_t)c[j] * OUT_F + lane * 4];
            uv[j] = *(const uint2*)&g_Vh[(size_t)c[j] * OUT_F + lane * 4];
        }
        float s[4];
        #pragma unroll
        for (int j = 0; j < 4; j++) {
            const float2 qa = __half22float2(*(const __half2*)&uq[j].x);
            const float2 qb = __half22float2(*(const __half2*)&uq[j].y);
            if (c[j] == r) {
                s[j] = kv.x * Dv.x * qa.x + kv.y * Dv.y * qa.y
                     + kv.z * Dv.z * qb.x + kv.w * Dv.w * qb.y;
            } else {
                float dx = kv.x - qa.x, dy = kv.y - qa.y, dz = kv.z - qb.x, dw = kv.w - qb.y;
                s[j] = dx * Dv.x * dx + dy * Dv.y * dy + dz * Dv.z * dz + dw * Dv.w * dw;
            }
        }
        #pragma unroll
        for (int mk = 1; mk <= 4; mk <<= 1)
            #pragma unroll
            for (int j = 0; j < 4; j++)
                s[j] += __shfl_xor_sync(0xffffffffu, s[j], mk);
        #pragma unroll
        for (int j = 0; j < 4; j++) {
            s[j] *= scale;
            s[j] = (s[j] > 0.f) ? s[j] : 0.2f * s[j];
            const float2 va = __half22float2(*(const __half2*)&uv[j].x);
            const float2 vb = __half22float2(*(const __half2*)&uv[j].y);
            float mn = fmaxf(m[j], s[j]);
            float cr = __expf(m[j] - mn), wgt = __expf(s[j] - mn);
            sw[j] = sw[j] * cr + wgt;
            A[j].x = A[j].x * cr + wgt * va.x; A[j].y = A[j].y * cr + wgt * va.y;
            A[j].z = A[j].z * cr + wgt * vb.x; A[j].w = A[j].w * cr + wgt * vb.y;
            m[j] = mn;
        }
    }
    for (; e < end; ++e) {
        const int c = g_src[e];
        const uint2 uq = *(const uint2*)&g_Qh[(size_t)c * OUT_F + lane * 4];
        const uint2 uv = *(const uint2*)&g_Vh[(size_t)c * OUT_F + lane * 4];
        const float2 qa = __half22float2(*(const __half2*)&uq.x);
        const float2 qb = __half22float2(*(const __half2*)&uq.y);
        float s;
        if (c == r) {
            s = kv.x * Dv.x * qa.x + kv.y * Dv.y * qa.y
              + kv.z * Dv.z * qb.x + kv.w * Dv.w * qb.y;
        } else {
            float dx = kv.x - qa.x, dy = kv.y - qa.y, dz = kv.z - qb.x, dw = kv.w - qb.y;
            s = dx * Dv.x * dx + dy * Dv.y * dy + dz * Dv.z * dz + dw * Dv.w * dw;
        }
        s += __shfl_xor_sync(0xffffffffu, s, 1);
        s += __shfl_xor_sync(0xffffffffu, s, 2);
        s += __shfl_xor_sync(0xffffffffu, s, 4);
        s *= scale;
        s = (s > 0.f) ? s : 0.2f * s;
        const float2 va = __half22float2(*(const __half2*)&uv.x);
        const float2 vb = __half22float2(*(const __half2*)&uv.y);
        float mn = fmaxf(m[0], s);
        float cr = __expf(m[0] - mn), wgt = __expf(s - mn);
        sw[0] = sw[0] * cr + wgt;
        A[0].x = A[0].x * cr + wgt * va.x; A[0].y = A[0].y * cr + wgt * va.y;
        A[0].z = A[0].z * cr + wgt * vb.x; A[0].w = A[0].w * cr + wgt * vb.y;
        m[0] = mn;
    }

    // merge states 1..3 into 0 (guard: empty state => sw==0)
    #pragma unroll
    for (int j = 1; j < 4; j++) {
        if (sw[j] != 0.f) {
            float mn = fmaxf(m[0], m[j]);
            float c0 = __expf(m[0] - mn), c1 = __expf(m[j] - mn);
            sw[0] = sw[0] * c0 + sw[j] * c1;
            A[0].x = A[0].x * c0 + A[j].x * c1; A[0].y = A[0].y * c0 + A[j].y * c1;
            A[0].z = A[0].z * c0 + A[j].z * c1; A[0].w = A[0].w * c0 + A[j].w * c1;
            m[0] = mn;
        }
    }

    const float inv = 1.f / (sw[0] + 1e-16f);
    float4 o = make_float4(A[0].x * inv, A[0].y * inv, A[0].z * inv, A[0].w * inv);
    *(float4*)&out[(size_t)r * OUT_F + lane * 4] = o;
}

// ---------------- launch -----------------
extern "C" void kernel_launch(void* const* d_in, const int* in_sizes, int n_in,
                              void* d_out, int out_size)
{
    const float *x = 0, *Wq = 0, *Wk = 0, *Wv = 0, *D = 0;
    const void  *ei = 0;
    int wcount = 0;
    for (int i = 0; i < n_in; i++) {
        long long sz = in_sizes[i];
        if (sz == (long long)N_NODES * IN_F) {
            x = (const float*)d_in[i];
        } else if (sz == (long long)2 * N_EDGES) {
            ei = d_in[i];
        } else if (sz == (long long)IN_F * OUT_F) {
            if (wcount == 0)      Wq = (const float*)d_in[i];
            else if (wcount == 1) Wk = (const float*)d_in[i];
            else                  Wv = (const float*)d_in[i];
            wcount++;
        } else if (sz == OUT_F) {
            D = (const float*)d_in[i];
        }
    }
    float* out = (float*)d_out;

    const int SMEM_DYN = 98304;   // Ah 32K + Al 32K + B 32K
    cudaFuncSetAttribute(qkv_hmma, cudaFuncAttributeMaxDynamicSharedMemorySize, SMEM_DYN);

    k_wconv<<<3, 128>>>(Wq, Wk, Wv);                          // 0
    k_zero<<<(N_NODES + 255) / 256, 256>>>(ei);               // 1
    k_count<<<(N_EDGES / 2 + 255) / 256, 256>>>(ei);          // 2
    qkv_hmma<<<NTILES, 256, SMEM_DYN>>>(x);                   // 3
    k_scanlb<<<NB_SCAN, 1024>>>();                            // 4
    k_scatter<<<(N_EDGES / 2 + 255) / 256, 256>>>(ei);        // 5
    k_aggregate<<<(N_NODES * 32 + 255) / 256, 256>>>(D, out); // 6
}

// round 16
// speedup vs baseline: 1.0096x; 1.0096x over previous
#include <cuda_runtime.h>
#include <cuda_fp16.h>
#include <math_constants.h>
#include <cstdint>

#define N_NODES 100000
#define N_EDGES 1600000
#define IN_F    128
#define OUT_F   128     // HEADS * D_K = 4 * 32
#define NB_SCAN ((N_NODES + 1023) / 1024)   // 98
#define NTILES  ((N_NODES + 127) / 128)     // 782

// ---------------- scratch (no allocations allowed) ----------------
__device__ __half g_Qh[N_NODES * OUT_F];    // Q gathered in fp16
__device__ float  g_K[N_NODES * OUT_F];     // K fp32 (read once per node)
__device__ __half g_Vh[N_NODES * OUT_F];    // V gathered in fp16
__device__ int    g_cnt[N_NODES];
__device__ int    g_off[N_NODES + 1];
__device__ int    g_cur[N_NODES];
__device__ int    g_src[N_EDGES];
__device__ int    g_bsum[128];
__device__ int    g_is64;
// single-fp16 weight images, row-major [out_feature][128]
__device__ __half g_Wh[3][OUT_F * IN_F];

// ---------------- mma.sync helpers (base sm_103 legal) ----------------
__device__ __forceinline__ uint32_t smem_u32(const void* p)
{
    uint32_t a;
    asm("{ .reg .u64 t; cvta.to.shared.u64 t, %1; cvt.u32.u64 %0, t; }"
        : "=r"(a) : "l"(p));
    return a;
}
__device__ __forceinline__ void ldsm4(uint32_t& r0, uint32_t& r1, uint32_t& r2,
                                      uint32_t& r3, uint32_t addr)
{
    asm volatile("ldmatrix.sync.aligned.m8n8.x4.shared.b16 {%0,%1,%2,%3}, [%4];"
                 : "=r"(r0), "=r"(r1), "=r"(r2), "=r"(r3) : "r"(addr));
}
__device__ __forceinline__ void mma16816(float* c,
                                         uint32_t a0, uint32_t a1, uint32_t a2, uint32_t a3,
                                         uint32_t b0, uint32_t b1)
{
    asm volatile("mma.sync.aligned.m16n8k16.row.col.f32.f16.f16.f32 "
                 "{%0,%1,%2,%3}, {%4,%5,%6,%7}, {%8,%9}, {%0,%1,%2,%3};"
                 : "+f"(c[0]), "+f"(c[1]), "+f"(c[2]), "+f"(c[3])
                 : "r"(a0), "r"(a1), "r"(a2), "r"(a3), "r"(b0), "r"(b1));
}
// 256B-row swizzled chunk offset: 16 chunks of 16B, low-3 chunk bits XOR row&7
__device__ __forceinline__ uint32_t sw256(int row, int ch)
{
    return (uint32_t)(row << 8) + (uint32_t)(((ch & 8) | ((ch & 7) ^ (row & 7))) << 4);
}

// zero counters + detect edge dtype (thread 0)
__global__ void k_zero(const void* __restrict__ ei)
{
    int i = blockIdx.x * blockDim.x + threadIdx.x;
    if (i < N_NODES) g_cnt[i] = 0;
    if (i == 0) {
        const long long* p = (const long long*)ei;
        bool ok = true;
        #pragma unroll
        for (int k = 0; k < 8; k++) {
            long long v = p[k];
            if (v < 0 || v >= N_NODES) ok = false;
        }
        g_is64 = ok ? 1 : 0;
    }
}

// ---------------- fp16 weight pre-conversion ----------------
__global__ void k_wconv(const float* __restrict__ Wq,
                        const float* __restrict__ Wk,
                        const float* __restrict__ Wv)
{
    int mat = blockIdx.x;
    const float* W = (mat == 0) ? Wq : (mat == 1) ? Wk : Wv;
    int row = threadIdx.x;            // output-feature 0..127
    #pragma unroll 4
    for (int c8 = 0; c8 < 16; c8++) {
        union { __half b[8]; uint4 v; } H;
        #pragma unroll
        for (int j = 0; j < 8; j++)
            H.b[j] = __float2half_rn(W[row * IN_F + c8 * 8 + j]);
        *(uint4*)&g_Wh[mat][row * IN_F + c8 * 8] = H.v;
    }
}

// ---------------- HMMA QKV GEMM ----------------
// grid (NTILES), 256 threads (8 warps, 32x64 warp tiles).
// A = x split into fp16 hi+lo (once per tile, full K in smem, 64KB);
// B = W single fp16 (32KB, reloaded per mat).
// Q,K: 2-term (Ahi+Alo)@B.  V: hi-only (fp16-stored anyway).
__global__ __launch_bounds__(256, 2) void qkv_hmma(const float* __restrict__ xp)
{
    extern __shared__ __align__(1024) unsigned char dsm[];
    const uint32_t sbase = smem_u32(dsm);
    const uint32_t Ah = sbase, Al = sbase + 32768, Bs = sbase + 65536;

    const int tile = blockIdx.x;
    const int tid = threadIdx.x, wid = tid >> 5, lane = tid & 31;
    const int wm = (wid & 3) * 32;        // warp M offset
    const int wn = (wid >> 2) * 64;       // warp N offset

    // ---- A: read x fp32 once, split fp16 hi/lo, store swizzled (full K) ----
    #pragma unroll
    for (int i = tid; i < 2048; i += 256) {
        int row = i >> 4, ch = i & 15;
        uint32_t dst = sw256(row, ch);
        int gr = tile * 128 + row;
        union { __half b[8]; uint4 v; } H, L;
        if (gr < N_NODES) {
            const float4 f0 = *(const float4*)&xp[(size_t)gr * IN_F + ch * 8 + 0];
            const float4 f1 = *(const float4*)&xp[(size_t)gr * IN_F + ch * 8 + 4];
            float fs[8] = {f0.x,f0.y,f0.z,f0.w,f1.x,f1.y,f1.z,f1.w};
            #pragma unroll
            for (int j = 0; j < 8; j++) {
                __half h = __float2half_rn(fs[j]);
                H.b[j] = h;
                L.b[j] = __float2half_rn(fs[j] - __half2float(h));
            }
        } else {
            H.v = make_uint4(0,0,0,0);
            L.v = make_uint4(0,0,0,0);
        }
        *(uint4*)(dsm + (Ah - sbase) + dst) = H.v;
        *(uint4*)(dsm + (Al - sbase) + dst) = L.v;
    }
    __syncthreads();

    for (int mat = 0; mat < 3; mat++) {
        const bool use_lo = (mat != 2);   // V: hi-only
        // ---- B: copy fp16 weights swizzled ----
        const __half* wsrc = g_Wh[mat];
        #pragma unroll
        for (int i = tid; i < 2048; i += 256) {
            int row = i >> 4, ch = i & 15;
            *(uint4*)(dsm + (Bs - sbase) + sw256(row, ch)) =
                *(const uint4*)&wsrc[(size_t)row * IN_F + ch * 8];
        }
        __syncthreads();

        float acc[2][8][4];
        #pragma unroll
        for (int mi = 0; mi < 2; mi++)
            #pragma unroll
            for (int nf = 0; nf < 8; nf++)
                #pragma unroll
                for (int j = 0; j < 4; j++) acc[mi][nf][j] = 0.f;

        #pragma unroll
        for (int k16 = 0; k16 < 8; k16++) {
            const int base8 = (k16 >> 2) << 3;
            const int c3 = ((k16 & 3) << 1) + (lane >> 4);
            uint32_t ah[2][4], al[2][4];
            #pragma unroll
            for (int mi = 0; mi < 2; mi++) {
                int arow = wm + mi * 16 + (lane & 15);
                uint32_t co = (uint32_t)((base8 + (c3 ^ (arow & 7))) << 4) + (uint32_t)(arow << 8);
                ldsm4(ah[mi][0], ah[mi][1], ah[mi][2], ah[mi][3], Ah + co);
                if (use_lo)
                    ldsm4(al[mi][0], al[mi][1], al[mi][2], al[mi][3], Al + co);
            }
            #pragma unroll
            for (int q = 0; q < 4; q++) {
                int brow = wn + q * 16 + (lane & 15);
                uint32_t b0, b1, b2, b3;
                ldsm4(b0, b1, b2, b3,
                      Bs + (uint32_t)(brow << 8) + (uint32_t)((base8 + (c3 ^ (brow & 7))) << 4));
                #pragma unroll
                for (int mi = 0; mi < 2; mi++) {
                    mma16816(acc[mi][q * 2 + 0], ah[mi][0], ah[mi][1], ah[mi][2], ah[mi][3], b0, b2);
                    mma16816(acc[mi][q * 2 + 1], ah[mi][0], ah[mi][1], ah[mi][2], ah[mi][3], b1, b3);
                    if (use_lo) {
                        mma16816(acc[mi][q * 2 + 0], al[mi][0], al[mi][1], al[mi][2], al[mi][3], b0, b2);
                        mma16816(acc[mi][q * 2 + 1], al[mi][0], al[mi][1], al[mi][2], al[mi][3], b1, b3);
                    }
                }
            }
        }
        __syncthreads();   // all MMAs done before B is overwritten next mat

        // ---- epilogue: c0,c1 -> (row t/4, col 2(t%4)); c2,c3 -> row+8 ----
        const int tq = lane >> 2, tr = lane & 3;
        #pragma unroll
        for (int mi = 0; mi < 2; mi++) {
            int r0 = tile * 128 + wm + mi * 16 + tq;
            #pragma unroll
            for (int nf = 0; nf < 8; nf++) {
                int col = wn + nf * 8 + tr * 2;
                if (mat == 1) {
                    if (r0 < N_NODES)
                        *(float2*)&g_K[(size_t)r0 * OUT_F + col] = make_float2(acc[mi][nf][0], acc[mi][nf][1]);
                    if (r0 + 8 < N_NODES)
                        *(float2*)&g_K[(size_t)(r0 + 8) * OUT_F + col] = make_float2(acc[mi][nf][2], acc[mi][nf][3]);
                } else {
                    __half* O = (mat == 0) ? g_Qh : g_Vh;
                    if (r0 < N_NODES)
                        *(__half2*)&O[(size_t)r0 * OUT_F + col] =
                            __floats2half2_rn(acc[mi][nf][0], acc[mi][nf][1]);
                    if (r0 + 8 < N_NODES)
                        *(__half2*)&O[(size_t)(r0 + 8) * OUT_F + col] =
                            __floats2half2_rn(acc[mi][nf][2], acc[mi][nf][3]);
                }
            }
        }
    }
}

// ---------------- CSR build -----------------
// 2 edges per thread, vectorized loads
__global__ void k_count(const void* __restrict__ ei)
{
    int e = (blockIdx.x * blockDim.x + threadIdx.x) * 2;
    if (e < N_EDGES) {
        int r0, r1;
        if (g_is64) {
            longlong2 p = *(const longlong2*)((const long long*)ei + e);
            r0 = (int)p.x; r1 = (int)p.y;
        } else {
            int2 p = *(const int2*)((const int*)ei + e);
            r0 = p.x; r1 = p.y;
        }
        if ((unsigned)r0 < N_NODES) atomicAdd(&g_cnt[r0], 1);
        if ((unsigned)r1 < N_NODES) atomicAdd(&g_cnt[r1], 1);
    }
}

__global__ __launch_bounds__(1024) void k_scan1()
{
    __shared__ int wsum[32];
    int i = blockIdx.x * 1024 + threadIdx.x;
    int v = (i < N_NODES) ? g_cnt[i] : 0;
    int lane = threadIdx.x & 31, w = threadIdx.x >> 5;

    int s = v;
    #pragma unroll
    for (int o = 1; o < 32; o <<= 1) {
        int t = __shfl_up_sync(0xffffffffu, s, o);
        if (lane >= o) s += t;
    }
    if (lane == 31) wsum[w] = s;
    __syncthreads();
    if (w == 0) {
        int t = wsum[lane];
        #pragma unroll
        for (int o = 1; o < 32; o <<= 1) {
            int u = __shfl_up_sync(0xffffffffu, t, o);
            if (lane >= o) t += u;
        }
        wsum[lane] = t;
    }
    __syncthreads();
    int excl = s - v + (w ? wsum[w - 1] : 0);
    if (i < N_NODES) g_off[i] = excl;
    if (threadIdx.x == 1023) g_bsum[blockIdx.x] = wsum[31];
}

__global__ void k_scan2()
{
    __shared__ int sm[128];
    int t = threadIdx.x;
    int v = (t < NB_SCAN) ? g_bsum[t] : 0;
    sm[t] = v;
    __syncthreads();
    for (int o = 1; o < 128; o <<= 1) {
        int u = (t >= o) ? sm[t - o] : 0;
        __syncthreads();
        sm[t] += u;
        __syncthreads();
    }
    if (t < NB_SCAN) g_bsum[t] = sm[t] - v;   // exclusive
    if (t == 127) g_off[N_NODES] = sm[127];
}

__global__ __launch_bounds__(1024) void k_scan3()
{
    int i = blockIdx.x * 1024 + threadIdx.x;
    if (i < N_NODES) {
        int o = g_off[i] + g_bsum[blockIdx.x];
        g_off[i] = o;
        g_cur[i] = o;
    }
}

__global__ void k_scatter(const void* __restrict__ ei)
{
    int e = (blockIdx.x * blockDim.x + threadIdx.x) * 2;
    if (e < N_EDGES) {
        int r0, r1, c0, c1;
        if (g_is64) {
            longlong2 pr = *(const longlong2*)((const long long*)ei + e);
            longlong2 pc = *(const longlong2*)((const long long*)ei + N_EDGES + e);
            r0 = (int)pr.x; r1 = (int)pr.y; c0 = (int)pc.x; c1 = (int)pc.y;
        } else {
            int2 pr = *(const int2*)((const int*)ei + e);
            int2 pc = *(const int2*)((const int*)ei + N_EDGES + e);
            r0 = pr.x; r1 = pr.y; c0 = pc.x; c1 = pc.y;
        }
        if ((unsigned)r0 < N_NODES && (unsigned)c0 < N_NODES) {
            int p = atomicAdd(&g_cur[r0], 1);
            g_src[p] = c0;
        }
        if ((unsigned)r1 < N_NODES && (unsigned)c1 < N_NODES) {
            int p = atomicAdd(&g_cur[r1], 1);
            g_src[p] = c1;
        }
    }
}

// ---------------- per-node online-softmax aggregation -------------
// TWO warps per destination node (halved serial chain), each warp runs the
// proven dual-stream loop over half the segment; SMEM merge at the end.
// Q fp16 (gathered), K fp32 (own node), V fp16.
// Grid: 25000 blocks x 8 warps = 200000 warps = 2 per node (exact).
__global__ __launch_bounds__(256) void k_aggregate(
    const float* __restrict__ D, float* __restrict__ out)
{
    __shared__ float  smM[4][32], smS[4][32];
    __shared__ float4 smA[4][32];

    const int wib  = threadIdx.x >> 5;   // 0..7
    const int lane = threadIdx.x & 31;
    const int pw   = wib >> 1;           // node slot in block 0..3
    const int half = wib & 1;
    const int r    = blockIdx.x * 4 + pw;   // always < N_NODES (25000*4)

    const int lo  = g_off[r];
    const int hi  = g_off[r + 1];
    const int mid = lo + ((hi - lo) >> 1);
    const int beg = half ? mid : lo;
    const int end = half ? hi : mid;

    const float4 kv = *(const float4*)&g_K[(size_t)r * OUT_F + lane * 4];
    const float4 Dv = *(const float4*)&D[lane * 4];
    const float scale = 0.1767766952966369f;   // 1/sqrt(32)

    float  m0 = -CUDART_INF_F, sw0 = 0.f;
    float  m1 = -CUDART_INF_F, sw1 = 0.f;
    float4 A0 = make_float4(0.f, 0.f, 0.f, 0.f);
    float4 A1 = make_float4(0.f, 0.f, 0.f, 0.f);

    int e = beg;
    for (; e + 2 <= end; e += 2) {
        const int c0 = g_src[e];
        const int c1 = g_src[e + 1];
        const uint2 uq0 = *(const uint2*)&g_Qh[(size_t)c0 * OUT_F + lane * 4];
        const uint2 uv0 = *(const uint2*)&g_Vh[(size_t)c0 * OUT_F + lane * 4];
        const uint2 uq1 = *(const uint2*)&g_Qh[(size_t)c1 * OUT_F + lane * 4];
        const uint2 uv1 = *(const uint2*)&g_Vh[(size_t)c1 * OUT_F + lane * 4];
        const float2 q0a = __half22float2(*(const __half2*)&uq0.x);
        const float2 q0b = __half22float2(*(const __half2*)&uq0.y);
        const float2 q1a = __half22float2(*(const __half2*)&uq1.x);
        const float2 q1b = __half22float2(*(const __half2*)&uq1.y);
        const float2 v0a = __half22float2(*(const __half2*)&uv0.x);
        const float2 v0b = __half22float2(*(const __half2*)&uv0.y);
        const float2 v1a = __half22float2(*(const __half2*)&uv1.x);
        const float2 v1b = __half22float2(*(const __half2*)&uv1.y);

        float s0, s1;
        if (c0 == r) {
            s0 = kv.x * Dv.x * q0a.x + kv.y * Dv.y * q0a.y
               + kv.z * Dv.z * q0b.x + kv.w * Dv.w * q0b.y;
        } else {
            float dx = kv.x - q0a.x, dy = kv.y - q0a.y, dz = kv.z - q0b.x, dw = kv.w - q0b.y;
            s0 = dx * Dv.x * dx + dy * Dv.y * dy + dz * Dv.z * dz + dw * Dv.w * dw;
        }
        if (c1 == r) {
            s1 = kv.x * Dv.x * q1a.x + kv.y * Dv.y * q1a.y
               + kv.z * Dv.z * q1b.x + kv.w * Dv.w * q1b.y;
        } else {
            float dx = kv.x - q1a.x, dy = kv.y - q1a.y, dz = kv.z - q1b.x, dw = kv.w - q1b.y;
            s1 = dx * Dv.x * dx + dy * Dv.y * dy + dz * Dv.z * dz + dw * Dv.w * dw;
        }
        s0 += __shfl_xor_sync(0xffffffffu, s0, 1);
        s1 += __shfl_xor_sync(0xffffffffu, s1, 1);
        s0 += __shfl_xor_sync(0xffffffffu, s0, 2);
        s1 += __shfl_xor_sync(0xffffffffu, s1, 2);
        s0 += __shfl_xor_sync(0xffffffffu, s0, 4);
        s1 += __shfl_xor_sync(0xffffffffu, s1, 4);
        s0 *= scale; s1 *= scale;
        s0 = (s0 > 0.f) ? s0 : 0.2f * s0;
        s1 = (s1 > 0.f) ? s1 : 0.2f * s1;

        {
            float mn = fmaxf(m0, s0);
            float cr = __expf(m0 - mn), w = __expf(s0 - mn);
            sw0 = sw0 * cr + w;
            A0.x = A0.x * cr + w * v0a.x; A0.y = A0.y * cr + w * v0a.y;
            A0.z = A0.z * cr + w * v0b.x; A0.w = A0.w * cr + w * v0b.y;
            m0 = mn;
        }
        {
            float mn = fmaxf(m1, s1);
            float cr = __expf(m1 - mn), w = __expf(s1 - mn);
            sw1 = sw1 * cr + w;
            A1.x = A1.x * cr + w * v1a.x; A1.y = A1.y * cr + w * v1a.y;
            A1.z = A1.z * cr + w * v1b.x; A1.w = A1.w * cr + w * v1b.y;
            m1 = mn;
        }
    }
    if (e < end) {
        const int c = g_src[e];
        const uint2 uq = *(const uint2*)&g_Qh[(size_t)c * OUT_F + lane * 4];
        const uint2 uv = *(const uint2*)&g_Vh[(size_t)c * OUT_F + lane * 4];
        const float2 qa = __half22float2(*(const __half2*)&uq.x);
        const float2 qb = __half22float2(*(const __half2*)&uq.y);
        const float2 va = __half22float2(*(const __half2*)&uv.x);
        const float2 vb = __half22float2(*(const __half2*)&uv.y);
        float s;
        if (c == r) {
            s = kv.x * Dv.x * qa.x + kv.y * Dv.y * qa.y
              + kv.z * Dv.z * qb.x + kv.w * Dv.w * qb.y;
        } else {
            float dx = kv.x - qa.x, dy = kv.y - qa.y, dz = kv.z - qb.x, dw = kv.w - qb.y;
            s = dx * Dv.x * dx + dy * Dv.y * dy + dz * Dv.z * dz + dw * Dv.w * dw;
        }
        s += __shfl_xor_sync(0xffffffffu, s, 1);
        s += __shfl_xor_sync(0xffffffffu, s, 2);
        s += __shfl_xor_sync(0xffffffffu, s, 4);
        s *= scale;
        s = (s > 0.f) ? s : 0.2f * s;
        float mn = fmaxf(m0, s);
        float cr = __expf(m0 - mn), w = __expf(s - mn);
        sw0 = sw0 * cr + w;
        A0.x = A0.x * cr + w * va.x; A0.y = A0.y * cr + w * va.y;
        A0.z = A0.z * cr + w * vb.x; A0.w = A0.w * cr + w * vb.y;
        m0 = mn;
    }

    // merge stream1 into stream0 (one-sided safe: exp(-inf - mn) = 0)
    if (sw1 != 0.f) {
        float mn = fmaxf(m0, m1);
        float c0 = __expf(m0 - mn), c1 = __expf(m1 - mn);
        sw0 = sw0 * c0 + sw1 * c1;
        A0.x = A0.x * c0 + A1.x * c1; A0.y = A0.y * c0 + A1.y * c1;
        A0.z = A0.z * c0 + A1.z * c1; A0.w = A0.w * c0 + A1.w * c1;
        m0 = mn;
    }

    // cross-warp merge via SMEM: half 1 publishes, half 0 merges + writes
    if (half == 1) {
        smM[pw][lane] = m0;
        smS[pw][lane] = sw0;
        smA[pw][lane] = A0;
    }
    __syncthreads();
    if (half == 0) {
        float  mB  = smM[pw][lane];
        float  swB = smS[pw][lane];
        float4 AB  = smA[pw][lane];
        if (swB != 0.f) {
            float mn = fmaxf(m0, mB);
            float c0 = __expf(m0 - mn), c1 = __expf(mB - mn);
            sw0 = sw0 * c0 + swB * c1;
            A0.x = A0.x * c0 + AB.x * c1; A0.y = A0.y * c0 + AB.y * c1;
            A0.z = A0.z * c0 + AB.z * c1; A0.w = A0.w * c0 + AB.w * c1;
        }
        const float inv = 1.f / (sw0 + 1e-16f);
        float4 o = make_float4(A0.x * inv, A0.y * inv, A0.z * inv, A0.w * inv);
        *(float4*)&out[(size_t)r * OUT_F + lane * 4] = o;
    }
}

// ---------------- launch -----------------
extern "C" void kernel_launch(void* const* d_in, const int* in_sizes, int n_in,
                              void* d_out, int out_size)
{
    const float *x = 0, *Wq = 0, *Wk = 0, *Wv = 0, *D = 0;
    const void  *ei = 0;
    int wcount = 0;
    for (int i = 0; i < n_in; i++) {
        long long sz = in_sizes[i];
        if (sz == (long long)N_NODES * IN_F) {
            x = (const float*)d_in[i];
        } else if (sz == (long long)2 * N_EDGES) {
            ei = d_in[i];
        } else if (sz == (long long)IN_F * OUT_F) {
            if (wcount == 0)      Wq = (const float*)d_in[i];
            else if (wcount == 1) Wk = (const float*)d_in[i];
            else                  Wv = (const float*)d_in[i];
            wcount++;
        } else if (sz == OUT_F) {
            D = (const float*)d_in[i];
        }
    }
    float* out = (float*)d_out;

    const int SMEM_DYN = 98304;   // Ah 32K + Al 32K + B 32K
    cudaFuncSetAttribute(qkv_hmma, cudaFuncAttributeMaxDynamicSharedMemorySize, SMEM_DYN);

    k_wconv<<<3, 128>>>(Wq, Wk, Wv);                          // 0
    k_zero<<<(N_NODES + 255) / 256, 256>>>(ei);               // 1
    k_count<<<(N_EDGES / 2 + 255) / 256, 256>>>(ei);          // 2
    qkv_hmma<<<NTILES, 256, SMEM_DYN>>>(x);                   // 3
    k_scan1<<<NB_SCAN, 1024>>>();                             // 4
    k_scan2<<<1, 128>>>();                                    // 5
    k_scan3<<<NB_SCAN, 1024>>>();                             // 6
    k_scatter<<<(N_EDGES / 2 + 255) / 256, 256>>>(ei);        // 7
    k_aggregate<<<25000, 256>>>(D, out);                      // 8
}

// round 17
// speedup vs baseline: 1.1413x; 1.1305x over previous
#include <cuda_runtime.h>
#include <cuda_fp16.h>
#include <math_constants.h>
#include <cstdint>

#define N_NODES 100000
#define N_EDGES 1600000
#define IN_F    128
#define OUT_F   128     // HEADS * D_K = 4 * 32
#define NB_SCAN ((N_NODES + 1023) / 1024)   // 98
#define NTILES  ((N_NODES + 127) / 128)     // 782

// ---------------- scratch (no allocations allowed) ----------------
__device__ __half g_Qh[N_NODES * OUT_F];    // Q gathered in fp16
__device__ float  g_K[N_NODES * OUT_F];     // K fp32 (read once per node)
__device__ __half g_Vh[N_NODES * OUT_F];    // V gathered in fp16
__device__ int    g_cnt[N_NODES];
__device__ int    g_off[N_NODES + 1];
__device__ int    g_cur[N_NODES];
__device__ int    g_src[N_EDGES];
__device__ int    g_bsum[128];
__device__ int    g_is64;
// single-fp16 weight images, row-major [out_feature][128]
__device__ __half g_Wh[3][OUT_F * IN_F];

// side stream + events, created at static-init (before harness mem checkpoints;
// nothing is created/destroyed inside kernel_launch or during capture)
struct SideStream {
    cudaStream_t s2;
    cudaEvent_t  fork, join;
    SideStream() {
        cudaStreamCreateWithFlags(&s2, cudaStreamNonBlocking);
        cudaEventCreateWithFlags(&fork, cudaEventDisableTiming);
        cudaEventCreateWithFlags(&join, cudaEventDisableTiming);
    }
};
static SideStream g_ss;

// ---------------- mma.sync helpers (base sm_103 legal) ----------------
__device__ __forceinline__ uint32_t smem_u32(const void* p)
{
    uint32_t a;
    asm("{ .reg .u64 t; cvta.to.shared.u64 t, %1; cvt.u32.u64 %0, t; }"
        : "=r"(a) : "l"(p));
    return a;
}
__device__ __forceinline__ void ldsm4(uint32_t& r0, uint32_t& r1, uint32_t& r2,
                                      uint32_t& r3, uint32_t addr)
{
    asm volatile("ldmatrix.sync.aligned.m8n8.x4.shared.b16 {%0,%1,%2,%3}, [%4];"
                 : "=r"(r0), "=r"(r1), "=r"(r2), "=r"(r3) : "r"(addr));
}
__device__ __forceinline__ void mma16816(float* c,
                                         uint32_t a0, uint32_t a1, uint32_t a2, uint32_t a3,
                                         uint32_t b0, uint32_t b1)
{
    asm volatile("mma.sync.aligned.m16n8k16.row.col.f32.f16.f16.f32 "
                 "{%0,%1,%2,%3}, {%4,%5,%6,%7}, {%8,%9}, {%0,%1,%2,%3};"
                 : "+f"(c[0]), "+f"(c[1]), "+f"(c[2]), "+f"(c[3])
                 : "r"(a0), "r"(a1), "r"(a2), "r"(a3), "r"(b0), "r"(b1));
}
// 256B-row swizzled chunk offset: 16 chunks of 16B, low-3 chunk bits XOR row&7
__device__ __forceinline__ uint32_t sw256(int row, int ch)
{
    return (uint32_t)(row << 8) + (uint32_t)(((ch & 8) | ((ch & 7) ^ (row & 7))) << 4);
}

// zero counters + detect edge dtype (thread 0)
__global__ void k_zero(const void* __restrict__ ei)
{
    int i = blockIdx.x * blockDim.x + threadIdx.x;
    if (i < N_NODES) g_cnt[i] = 0;
    if (i == 0) {
        const long long* p = (const long long*)ei;
        bool ok = true;
        #pragma unroll
        for (int k = 0; k < 8; k++) {
            long long v = p[k];
            if (v < 0 || v >= N_NODES) ok = false;
        }
        g_is64 = ok ? 1 : 0;
    }
}

// ---------------- fp16 weight pre-conversion ----------------
__global__ void k_wconv(const float* __restrict__ Wq,
                        const float* __restrict__ Wk,
                        const float* __restrict__ Wv)
{
    int mat = blockIdx.x;
    const float* W = (mat == 0) ? Wq : (mat == 1) ? Wk : Wv;
    int row = threadIdx.x;            // output-feature 0..127
    #pragma unroll 4
    for (int c8 = 0; c8 < 16; c8++) {
        union { __half b[8]; uint4 v; } H;
        #pragma unroll
        for (int j = 0; j < 8; j++)
            H.b[j] = __float2half_rn(W[row * IN_F + c8 * 8 + j]);
        *(uint4*)&g_Wh[mat][row * IN_F + c8 * 8] = H.v;
    }
}

// ---------------- HMMA QKV GEMM ----------------
// grid (NTILES), 256 threads (8 warps, 32x64 warp tiles).
// A = x split into fp16 hi+lo (once per tile, full K in smem, 64KB);
// B = W single fp16 (32KB, reloaded per mat).
// Q,K: 2-term (Ahi+Alo)@B.  V: hi-only (fp16-stored anyway).
__global__ __launch_bounds__(256, 2) void qkv_hmma(const float* __restrict__ xp)
{
    extern __shared__ __align__(1024) unsigned char dsm[];
    const uint32_t sbase = smem_u32(dsm);
    const uint32_t Ah = sbase, Al = sbase + 32768, Bs = sbase + 65536;

    const int tile = blockIdx.x;
    const int tid = threadIdx.x, wid = tid >> 5, lane = tid & 31;
    const int wm = (wid & 3) * 32;        // warp M offset
    const int wn = (wid >> 2) * 64;       // warp N offset

    // ---- A: read x fp32 once, split fp16 hi/lo, store swizzled (full K) ----
    #pragma unroll
    for (int i = tid; i < 2048; i += 256) {
        int row = i >> 4, ch = i & 15;
        uint32_t dst = sw256(row, ch);
        int gr = tile * 128 + row;
        union { __half b[8]; uint4 v; } H, L;
        if (gr < N_NODES) {
            const float4 f0 = *(const float4*)&xp[(size_t)gr * IN_F + ch * 8 + 0];
            const float4 f1 = *(const float4*)&xp[(size_t)gr * IN_F + ch * 8 + 4];
            float fs[8] = {f0.x,f0.y,f0.z,f0.w,f1.x,f1.y,f1.z,f1.w};
            #pragma unroll
            for (int j = 0; j < 8; j++) {
                __half h = __float2half_rn(fs[j]);
                H.b[j] = h;
                L.b[j] = __float2half_rn(fs[j] - __half2float(h));
            }
        } else {
            H.v = make_uint4(0,0,0,0);
            L.v = make_uint4(0,0,0,0);
        }
        *(uint4*)(dsm + (Ah - sbase) + dst) = H.v;
        *(uint4*)(dsm + (Al - sbase) + dst) = L.v;
    }
    __syncthreads();

    for (int mat = 0; mat < 3; mat++) {
        const bool use_lo = (mat != 2);   // V: hi-only
        // ---- B: copy fp16 weights swizzled ----
        const __half* wsrc = g_Wh[mat];
        #pragma unroll
        for (int i = tid; i < 2048; i += 256) {
            int row = i >> 4, ch = i & 15;
            *(uint4*)(dsm + (Bs - sbase) + sw256(row, ch)) =
                *(const uint4*)&wsrc[(size_t)row * IN_F + ch * 8];
        }
        __syncthreads();

        float acc[2][8][4];
        #pragma unroll
        for (int mi = 0; mi < 2; mi++)
            #pragma unroll
            for (int nf = 0; nf < 8; nf++)
                #pragma unroll
                for (int j = 0; j < 4; j++) acc[mi][nf][j] = 0.f;

        #pragma unroll
        for (int k16 = 0; k16 < 8; k16++) {
            const int base8 = (k16 >> 2) << 3;
            const int c3 = ((k16 & 3) << 1) + (lane >> 4);
            uint32_t ah[2][4], al[2][4];
            #pragma unroll
            for (int mi = 0; mi < 2; mi++) {
                int arow = wm + mi * 16 + (lane & 15);
                uint32_t co = (uint32_t)((base8 + (c3 ^ (arow & 7))) << 4) + (uint32_t)(arow << 8);
                ldsm4(ah[mi][0], ah[mi][1], ah[mi][2], ah[mi][3], Ah + co);
                if (use_lo)
                    ldsm4(al[mi][0], al[mi][1], al[mi][2], al[mi][3], Al + co);
            }
            #pragma unroll
            for (int q = 0; q < 4; q++) {
                int brow = wn + q * 16 + (lane & 15);
                uint32_t b0, b1, b2, b3;
                ldsm4(b0, b1, b2, b3,
                      Bs + (uint32_t)(brow << 8) + (uint32_t)((base8 + (c3 ^ (brow & 7))) << 4));
                #pragma unroll
                for (int mi = 0; mi < 2; mi++) {
                    mma16816(acc[mi][q * 2 + 0], ah[mi][0], ah[mi][1], ah[mi][2], ah[mi][3], b0, b2);
                    mma16816(acc[mi][q * 2 + 1], ah[mi][0], ah[mi][1], ah[mi][2], ah[mi][3], b1, b3);
                    if (use_lo) {
                        mma16816(acc[mi][q * 2 + 0], al[mi][0], al[mi][1], al[mi][2], al[mi][3], b0, b2);
                        mma16816(acc[mi][q * 2 + 1], al[mi][0], al[mi][1], al[mi][2], al[mi][3], b1, b3);
                    }
                }
            }
        }
        __syncthreads();   // all MMAs done before B is overwritten next mat

        // ---- epilogue: c0,c1 -> (row t/4, col 2(t%4)); c2,c3 -> row+8 ----
        const int tq = lane >> 2, tr = lane & 3;
        #pragma unroll
        for (int mi = 0; mi < 2; mi++) {
            int r0 = tile * 128 + wm + mi * 16 + tq;
            #pragma unroll
            for (int nf = 0; nf < 8; nf++) {
                int col = wn + nf * 8 + tr * 2;
                if (mat == 1) {
                    if (r0 < N_NODES)
                        *(float2*)&g_K[(size_t)r0 * OUT_F + col] = make_float2(acc[mi][nf][0], acc[mi][nf][1]);
                    if (r0 + 8 < N_NODES)
                        *(float2*)&g_K[(size_t)(r0 + 8) * OUT_F + col] = make_float2(acc[mi][nf][2], acc[mi][nf][3]);
                } else {
                    __half* O = (mat == 0) ? g_Qh : g_Vh;
                    if (r0 < N_NODES)
                        *(__half2*)&O[(size_t)r0 * OUT_F + col] =
                            __floats2half2_rn(acc[mi][nf][0], acc[mi][nf][1]);
                    if (r0 + 8 < N_NODES)
                        *(__half2*)&O[(size_t)(r0 + 8) * OUT_F + col] =
                            __floats2half2_rn(acc[mi][nf][2], acc[mi][nf][3]);
                }
            }
        }
    }
}

// ---------------- CSR build -----------------
// 2 edges per thread, vectorized loads
__global__ void k_count(const void* __restrict__ ei)
{
    int e = (blockIdx.x * blockDim.x + threadIdx.x) * 2;
    if (e < N_EDGES) {
        int r0, r1;
        if (g_is64) {
            longlong2 p = *(const longlong2*)((const long long*)ei + e);
            r0 = (int)p.x; r1 = (int)p.y;
        } else {
            int2 p = *(const int2*)((const int*)ei + e);
            r0 = p.x; r1 = p.y;
        }
        if ((unsigned)r0 < N_NODES) atomicAdd(&g_cnt[r0], 1);
        if ((unsigned)r1 < N_NODES) atomicAdd(&g_cnt[r1], 1);
    }
}

__global__ __launch_bounds__(1024) void k_scan1()
{
    __shared__ int wsum[32];
    int i = blockIdx.x * 1024 + threadIdx.x;
    int v = (i < N_NODES) ? g_cnt[i] : 0;
    int lane = threadIdx.x & 31, w = threadIdx.x >> 5;

    int s = v;
    #pragma unroll
    for (int o = 1; o < 32; o <<= 1) {
        int t = __shfl_up_sync(0xffffffffu, s, o);
        if (lane >= o) s += t;
    }
    if (lane == 31) wsum[w] = s;
    __syncthreads();
    if (w == 0) {
        int t = wsum[lane];
        #pragma unroll
        for (int o = 1; o < 32; o <<= 1) {
            int u = __shfl_up_sync(0xffffffffu, t, o);
            if (lane >= o) t += u;
        }
        wsum[lane] = t;
    }
    __syncthreads();
    int excl = s - v + (w ? wsum[w - 1] : 0);
    if (i < N_NODES) g_off[i] = excl;
    if (threadIdx.x == 1023) g_bsum[blockIdx.x] = wsum[31];
}

__global__ void k_scan2()
{
    __shared__ int sm[128];
    int t = threadIdx.x;
    int v = (t < NB_SCAN) ? g_bsum[t] : 0;
    sm[t] = v;
    __syncthreads();
    for (int o = 1; o < 128; o <<= 1) {
        int u = (t >= o) ? sm[t - o] : 0;
        __syncthreads();
        sm[t] += u;
        __syncthreads();
    }
    if (t < NB_SCAN) g_bsum[t] = sm[t] - v;   // exclusive
    if (t == 127) g_off[N_NODES] = sm[127];
}

__global__ __launch_bounds__(1024) void k_scan3()
{
    int i = blockIdx.x * 1024 + threadIdx.x;
    if (i < N_NODES) {
        int o = g_off[i] + g_bsum[blockIdx.x];
        g_off[i] = o;
        g_cur[i] = o;
    }
}

__global__ void k_scatter(const void* __restrict__ ei)
{
    int e = (blockIdx.x * blockDim.x + threadIdx.x) * 2;
    if (e < N_EDGES) {
        int r0, r1, c0, c1;
        if (g_is64) {
            longlong2 pr = *(const longlong2*)((const long long*)ei + e);
            longlong2 pc = *(const longlong2*)((const long long*)ei + N_EDGES + e);
            r0 = (int)pr.x; r1 = (int)pr.y; c0 = (int)pc.x; c1 = (int)pc.y;
        } else {
            int2 pr = *(const int2*)((const int*)ei + e);
            int2 pc = *(const int2*)((const int*)ei + N_EDGES + e);
            r0 = pr.x; r1 = pr.y; c0 = pc.x; c1 = pc.y;
        }
        if ((unsigned)r0 < N_NODES && (unsigned)c0 < N_NODES) {
            int p = atomicAdd(&g_cur[r0], 1);
            g_src[p] = c0;
        }
        if ((unsigned)r1 < N_NODES && (unsigned)c1 < N_NODES) {
            int p = atomicAdd(&g_cur[r1], 1);
            g_src[p] = c1;
        }
    }
}

// ---------------- per-node online-softmax aggregation -------------
// One warp per destination node; dual edge streams (R14-proven).
// Q fp16 (gathered), K fp32 (own node), V fp16.
__global__ __launch_bounds__(256) void k_aggregate(
    const float* __restrict__ D, float* __restrict__ out)
{
    int warp = (blockIdx.x * blockDim.x + threadIdx.x) >> 5;
    int lane = threadIdx.x & 31;
    if (warp >= N_NODES) return;
    const int r = warp;

    const int beg = g_off[r];
    const int end = g_off[r + 1];

    const float4 kv = *(const float4*)&g_K[(size_t)r * OUT_F + lane * 4];
    const float4 Dv = *(const float4*)&D[lane * 4];
    const float scale = 0.1767766952966369f;   // 1/sqrt(32)

    float  m0 = -CUDART_INF_F, sw0 = 0.f;
    float  m1 = -CUDART_INF_F, sw1 = 0.f;
    float4 A0 = make_float4(0.f, 0.f, 0.f, 0.f);
    float4 A1 = make_float4(0.f, 0.f, 0.f, 0.f);

    int e = beg;
    for (; e + 2 <= end; e += 2) {
        const int c0 = g_src[e];
        const int c1 = g_src[e + 1];
        const uint2 uq0 = *(const uint2*)&g_Qh[(size_t)c0 * OUT_F + lane * 4];
        const uint2 uv0 = *(const uint2*)&g_Vh[(size_t)c0 * OUT_F + lane * 4];
        const uint2 uq1 = *(const uint2*)&g_Qh[(size_t)c1 * OUT_F + lane * 4];
        const uint2 uv1 = *(const uint2*)&g_Vh[(size_t)c1 * OUT_F + lane * 4];
        const float2 q0a = __half22float2(*(const __half2*)&uq0.x);
        const float2 q0b = __half22float2(*(const __half2*)&uq0.y);
        const float2 q1a = __half22float2(*(const __half2*)&uq1.x);
        const float2 q1b = __half22float2(*(const __half2*)&uq1.y);
        const float2 v0a = __half22float2(*(const __half2*)&uv0.x);
        const float2 v0b = __half22float2(*(const __half2*)&uv0.y);
        const float2 v1a = __half22float2(*(const __half2*)&uv1.x);
        const float2 v1b = __half22float2(*(const __half2*)&uv1.y);

        float s0, s1;
        if (c0 == r) {
            s0 = kv.x * Dv.x * q0a.x + kv.y * Dv.y * q0a.y
               + kv.z * Dv.z * q0b.x + kv.w * Dv.w * q0b.y;
        } else {
            float dx = kv.x - q0a.x, dy = kv.y - q0a.y, dz = kv.z - q0b.x, dw = kv.w - q0b.y;
            s0 = dx * Dv.x * dx + dy * Dv.y * dy + dz * Dv.z * dz + dw * Dv.w * dw;
        }
        if (c1 == r) {
            s1 = kv.x * Dv.x * q1a.x + kv.y * Dv.y * q1a.y
               + kv.z * Dv.z * q1b.x + kv.w * Dv.w * q1b.y;
        } else {
            float dx = kv.x - q1a.x, dy = kv.y - q1a.y, dz = kv.z - q1b.x, dw = kv.w - q1b.y;
            s1 = dx * Dv.x * dx + dy * Dv.y * dy + dz * Dv.z * dz + dw * Dv.w * dw;
        }
        s0 += __shfl_xor_sync(0xffffffffu, s0, 1);
        s1 += __shfl_xor_sync(0xffffffffu, s1, 1);
        s0 += __shfl_xor_sync(0xffffffffu, s0, 2);
        s1 += __shfl_xor_sync(0xffffffffu, s1, 2);
        s0 += __shfl_xor_sync(0xffffffffu, s0, 4);
        s1 += __shfl_xor_sync(0xffffffffu, s1, 4);
        s0 *= scale; s1 *= scale;
        s0 = (s0 > 0.f) ? s0 : 0.2f * s0;
        s1 = (s1 > 0.f) ? s1 : 0.2f * s1;

        {
            float mn = fmaxf(m0, s0);
            float cr = __expf(m0 - mn), w = __expf(s0 - mn);
            sw0 = sw0 * cr + w;
            A0.x = A0.x * cr + w * v0a.x; A0.y = A0.y * cr + w * v0a.y;
            A0.z = A0.z * cr + w * v0b.x; A0.w = A0.w * cr + w * v0b.y;
            m0 = mn;
        }
        {
            float mn = fmaxf(m1, s1);
            float cr = __expf(m1 - mn), w = __expf(s1 - mn);
            sw1 = sw1 * cr + w;
            A1.x = A1.x * cr + w * v1a.x; A1.y = A1.y * cr + w * v1a.y;
            A1.z = A1.z * cr + w * v1b.x; A1.w = A1.w * cr + w * v1b.y;
            m1 = mn;
        }
    }
    if (e < end) {
        const int c = g_src[e];
        const uint2 uq = *(const uint2*)&g_Qh[(size_t)c * OUT_F + lane * 4];
        const uint2 uv = *(const uint2*)&g_Vh[(size_t)c * OUT_F + lane * 4];
        const float2 qa = __half22float2(*(const __half2*)&uq.x);
        const float2 qb = __half22float2(*(const __half2*)&uq.y);
        const float2 va = __half22float2(*(const __half2*)&uv.x);
        const float2 vb = __half22float2(*(const __half2*)&uv.y);
        float s;
        if (c == r) {
            s = kv.x * Dv.x * qa.x + kv.y * Dv.y * qa.y
              + kv.z * Dv.z * qb.x + kv.w * Dv.w * qb.y;
        } else {
            float dx = kv.x - qa.x, dy = kv.y - qa.y, dz = kv.z - qb.x, dw = kv.w - qb.y;
            s = dx * Dv.x * dx + dy * Dv.y * dy + dz * Dv.z * dz + dw * Dv.w * dw;
        }
        s += __shfl_xor_sync(0xffffffffu, s, 1);
        s += __shfl_xor_sync(0xffffffffu, s, 2);
        s += __shfl_xor_sync(0xffffffffu, s, 4);
        s *= scale;
        s = (s > 0.f) ? s : 0.2f * s;
        float mn = fmaxf(m0, s);
        float cr = __expf(m0 - mn), w = __expf(s - mn);
        sw0 = sw0 * cr + w;
        A0.x = A0.x * cr + w * va.x; A0.y = A0.y * cr + w * va.y;
        A0.z = A0.z * cr + w * vb.x; A0.w = A0.w * cr + w * vb.y;
        m0 = mn;
    }

    // merge state1 into state0 (state1 nonempty implies state0 nonempty)
    if (sw1 != 0.f) {
        float mn = fmaxf(m0, m1);
        float c0 = __expf(m0 - mn), c1 = __expf(m1 - mn);
        sw0 = sw0 * c0 + sw1 * c1;
        A0.x = A0.x * c0 + A1.x * c1; A0.y = A0.y * c0 + A1.y * c1;
        A0.z = A0.z * c0 + A1.z * c1; A0.w = A0.w * c0 + A1.w * c1;
    }

    const float inv = 1.f / (sw0 + 1e-16f);
    float4 o = make_float4(A0.x * inv, A0.y * inv, A0.z * inv, A0.w * inv);
    *(float4*)&out[(size_t)r * OUT_F + lane * 4] = o;
}

// ---------------- launch -----------------
extern "C" void kernel_launch(void* const* d_in, const int* in_sizes, int n_in,
                              void* d_out, int out_size)
{
    const float *x = 0, *Wq = 0, *Wk = 0, *Wv = 0, *D = 0;
    const void  *ei = 0;
    int wcount = 0;
    for (int i = 0; i < n_in; i++) {
        long long sz = in_sizes[i];
        if (sz == (long long)N_NODES * IN_F) {
            x = (const float*)d_in[i];
        } else if (sz == (long long)2 * N_EDGES) {
            ei = d_in[i];
        } else if (sz == (long long)IN_F * OUT_F) {
            if (wcount == 0)      Wq = (const float*)d_in[i];
            else if (wcount == 1) Wk = (const float*)d_in[i];
            else                  Wv = (const float*)d_in[i];
            wcount++;
        } else if (sz == OUT_F) {
            D = (const float*)d_in[i];
        }
    }
    float* out = (float*)d_out;

    const int SMEM_DYN = 98304;   // Ah 32K + Al 32K + B 32K
    cudaFuncSetAttribute(qkv_hmma, cudaFuncAttributeMaxDynamicSharedMemorySize, SMEM_DYN);

    // fork: CSR chain on side stream, GEMM chain on main stream
    cudaEventRecord(g_ss.fork, 0);
    cudaStreamWaitEvent(g_ss.s2, g_ss.fork, 0);

    // side stream: CSR build
    k_zero<<<(N_NODES + 255) / 256, 256, 0, g_ss.s2>>>(ei);
    k_count<<<(N_EDGES / 2 + 255) / 256, 256, 0, g_ss.s2>>>(ei);
    k_scan1<<<NB_SCAN, 1024, 0, g_ss.s2>>>();
    k_scan2<<<1, 128, 0, g_ss.s2>>>();
    k_scan3<<<NB_SCAN, 1024, 0, g_ss.s2>>>();
    k_scatter<<<(N_EDGES / 2 + 255) / 256, 256, 0, g_ss.s2>>>(ei);
    cudaEventRecord(g_ss.join, g_ss.s2);

    // main stream: QKV projection
    k_wconv<<<3, 128>>>(Wq, Wk, Wv);
    qkv_hmma<<<NTILES, 256, SMEM_DYN>>>(x);

    // join, then aggregate
    cudaStreamWaitEvent(0, g_ss.join, 0);
    k_aggregate<<<(N_NODES * 32 + 255) / 256, 256>>>(D, out);
}